// round 15
// baseline (speedup 1.0000x reference)
#include <cuda_runtime.h>
#include <cuda_fp16.h>
#include <cstdint>
#include <cstddef>

typedef __half fp16;

#define T_TOK   1024
#define H_DIM   1024
#define I_DIM   2816
#define E_NUM   8
#define NPAIR   2048
#define W13_2I  5632

// ---------------------------------------------------------------------------
// Device scratch (referenced ONLY from device code)
// ---------------------------------------------------------------------------
__device__ fp16 g_w2t [(size_t)E_NUM * H_DIM * I_DIM];   // [E,H,I] K-major fp16
__device__ fp16 g_hid_hi[(size_t)T_TOK * H_DIM];
__device__ fp16 g_hid_lo[(size_t)T_TOK * H_DIM];
__device__ fp16 g_act_hi[(size_t)NPAIR * I_DIM];
__device__ fp16 g_act_lo[(size_t)NPAIR * I_DIM];
__device__ float g_eo   [(size_t)NPAIR * H_DIM];
__device__ float g_wt   [NPAIR];
__device__ int   g_cnt  [E_NUM];
__device__ int   g_list [E_NUM * T_TOK];

// ---------------------------------------------------------------------------
// PTX helpers (sm_80-compatible only)
// ---------------------------------------------------------------------------
__device__ __forceinline__ uint32_t s2u(const void* p) {
    uint32_t a;
    asm("{ .reg .u64 t; cvta.to.shared.u64 t, %1; cvt.u32.u64 %0, t; }"
        : "=r"(a) : "l"(p));
    return a;
}
__device__ __forceinline__ uint32_t sw128(uint32_t o) { return o ^ ((o >> 3) & 0x70); }

__device__ __forceinline__ void cp16(uint32_t dst, const void* src) {
    asm volatile("cp.async.cg.shared.global [%0], [%1], 16;" :: "r"(dst), "l"(src));
}
__device__ __forceinline__ void cp_commit() { asm volatile("cp.async.commit_group;"); }
template<int N> __device__ __forceinline__ void cp_wait() {
    asm volatile("cp.async.wait_group %0;" :: "n"(N));
}

#define LDSM4(r, addr) asm volatile( \
    "ldmatrix.sync.aligned.m8n8.x4.shared.b16 {%0,%1,%2,%3}, [%4];" \
    : "=r"((r)[0]), "=r"((r)[1]), "=r"((r)[2]), "=r"((r)[3]) : "r"(addr))

#define LDSM4T(r, addr) asm volatile( \
    "ldmatrix.sync.aligned.m8n8.x4.trans.shared.b16 {%0,%1,%2,%3}, [%4];" \
    : "=r"((r)[0]), "=r"((r)[1]), "=r"((r)[2]), "=r"((r)[3]) : "r"(addr))

__device__ __forceinline__ void mma_f16(float* c, const uint32_t* a,
                                        uint32_t b0, uint32_t b1) {
    asm volatile(
        "mma.sync.aligned.m16n8k16.row.col.f32.f16.f16.f32 "
        "{%0,%1,%2,%3}, {%4,%5,%6,%7}, {%8,%9}, {%0,%1,%2,%3};"
        : "+f"(c[0]), "+f"(c[1]), "+f"(c[2]), "+f"(c[3])
        : "r"(a[0]), "r"(a[1]), "r"(a[2]), "r"(a[3]), "r"(b0), "r"(b1));
}

__device__ __forceinline__ void sts8_h2(char* p, float x, float y, float z, float w) {
    __half2 h[2];
    h[0] = __floats2half2_rn(x, y);
    h[1] = __floats2half2_rn(z, w);
    *(uint2*)p = *(uint2*)h;
}

#define KT 64                 // fp16 per K-stage (128-byte rows)
#define TILE_T 16384          // 128 x 64 fp16
#define BTILE_T 8192          // 64 x 64 fp16

// ---------------------------------------------------------------------------
// Fused prep: blocks 0..1023 split hidden fp32 -> fp16 hi/lo;
// block 1024 runs the router (1024 threads, one per token).
// ---------------------------------------------------------------------------
__global__ __launch_bounds__(1024) void prep_kernel(
    const float* __restrict__ h, const float* __restrict__ logits)
{
    if (blockIdx.x < 1024) {
        int i = blockIdx.x * 1024 + threadIdx.x;
        float v = h[i];
        fp16 hi = __float2half_rn(v);
        g_hid_hi[i] = hi;
        g_hid_lo[i] = __float2half_rn(v - __half2float(hi));
        return;
    }

    int t = threadIdx.x;
    if (t < E_NUM) g_cnt[t] = 0;
    __syncthreads();

    float l[E_NUM];
#pragma unroll
    for (int i = 0; i < E_NUM; ++i) l[i] = logits[t * E_NUM + i];

    int i0 = 0;
#pragma unroll
    for (int i = 1; i < E_NUM; ++i) if (l[i] > l[i0]) i0 = i;
    int i1 = (i0 == 0) ? 1 : 0;
#pragma unroll
    for (int i = 0; i < E_NUM; ++i) {
        if (i == i0) continue;
        if (l[i] > l[i1]) i1 = i;
    }
    float e1 = expf(l[i1] - l[i0]);
    float w0 = 1.0f / (1.0f + e1);
    g_wt[2 * t]     = w0;
    g_wt[2 * t + 1] = 1.0f - w0;

    int s0 = atomicAdd(&g_cnt[i0], 1);
    g_list[i0 * T_TOK + s0] = 2 * t;
    int s1 = atomicAdd(&g_cnt[i1], 1);
    g_list[i1 * T_TOK + s1] = 2 * t + 1;
}

// ---------------------------------------------------------------------------
// w2 [E, I, H] fp32 -> g_w2t [E, H, I] fp16 (K-major for GEMM2 B).
// 64x64 tile, 256 threads, float4 loads, half2 coalesced stores.
// ---------------------------------------------------------------------------
__global__ __launch_bounds__(256) void trans_w2(const float* __restrict__ in)
{
    __shared__ float ts[64 * 65];
    const int e = blockIdx.z;
    const float* I = in + (size_t)e * I_DIM * H_DIM;
    fp16* O = g_w2t + (size_t)e * H_DIM * I_DIM;
    const int c0 = blockIdx.x * 64;   // col in [0, H)
    const int r0 = blockIdx.y * 64;   // row in [0, I)

    const int xq = threadIdx.x & 15;
    const int yr = threadIdx.x >> 4;
#pragma unroll
    for (int i = 0; i < 4; ++i) {
        int r = yr + 16 * i;
        float4 v = *(const float4*)&I[(size_t)(r0 + r) * H_DIM + c0 + xq * 4];
        ts[(xq * 4 + 0) * 65 + r] = v.x;
        ts[(xq * 4 + 1) * 65 + r] = v.y;
        ts[(xq * 4 + 2) * 65 + r] = v.z;
        ts[(xq * 4 + 3) * 65 + r] = v.w;
    }
    __syncthreads();

    const int wid = threadIdx.x >> 5;
    const int l = threadIdx.x & 31;
#pragma unroll
    for (int i = 0; i < 8; ++i) {
        int cl = wid * 8 + i;
        float f0 = ts[cl * 65 + 2 * l];
        float f1 = ts[cl * 65 + 2 * l + 1];
        size_t ob = (size_t)(c0 + cl) * I_DIM + r0 + 2 * l;
        *(__half2*)&O[ob] = __floats2half2_rn(f0, f1);
    }
}

// ---------------------------------------------------------------------------
// GEMM1: CTA M=128 tokens, N=64 gate + 64 up cols. 256 threads (8 warps),
// warp = 64(M) x 16(N) of both gate and up. A = split fp16 via cp.async.
// B = fp32 weights loaded DIRECTLY from w13 [H,2I] (no transpose kernel):
// float4 LDG -> half2 STS into [k][n] SW128 tiles -> ldmatrix.x4.trans.
// smem: 1024 + 2 x 48KB = 99328.
// ---------------------------------------------------------------------------
#define G1_STAGE (2 * TILE_T + 2 * BTILE_T)      // 48 KB
#define G1_SMEM  (1024 + 2 * G1_STAGE)

__global__ __launch_bounds__(256, 1) void gemm1_kernel(const float* __restrict__ w13)
{
    extern __shared__ char smem[];
    const uint32_t sb = s2u(smem);
    const int tid = threadIdx.x;
    const int lid = tid & 31, wid = tid >> 5;
    const int wm = wid >> 2;          // 0..1 -> 64 rows
    const int wn = wid & 3;           // 0..3 -> 16 cols
    const int e  = blockIdx.z;
    const int n_e = g_cnt[e];
    const int y0 = blockIdx.x * 128;
    if (y0 >= n_e) return;
    const int n0 = blockIdx.y * 64;

    int* pid_s = (int*)smem;
    if (tid < 128) {
        int r = y0 + tid;
        pid_s[tid] = (r < n_e) ? g_list[e * T_TOK + r] : 0;
    }
    __syncthreads();

    const float* We = w13 + (size_t)e * H_DIM * W13_2I;

    // B staging: thread loads 4 float4 per tile (G and U)
    const int bn4 = (tid & 15) * 4;   // n offset 0..60
    const int bkb = tid >> 4;         // k row 0..15 (x4 passes)
    float4 rG[4], rU[4];

    auto ldgB = [&](int s) {
        const int k0 = s * KT;
#pragma unroll
        for (int p = 0; p < 4; ++p) {
            const float* src = We + (size_t)(k0 + bkb + 16 * p) * W13_2I + n0 + bn4;
            rG[p] = *(const float4*)src;
            rU[p] = *(const float4*)(src + I_DIM);
        }
    };
    auto stsB = [&](int s) {
        char* bufg = smem + 1024 + (s & 1) * G1_STAGE + 2 * TILE_T;
#pragma unroll
        for (int p = 0; p < 4; ++p) {
            uint32_t o = sw128((uint32_t)((bkb + 16 * p) * 128 + bn4 * 2));
            sts8_h2(bufg + o,           rG[p].x, rG[p].y, rG[p].z, rG[p].w);
            sts8_h2(bufg + BTILE_T + o, rU[p].x, rU[p].y, rU[p].z, rU[p].w);
        }
    };
    auto prefA = [&](int s) {
        const int k0 = s * KT;
        const uint32_t buf = sb + 1024 + (uint32_t)(s & 1) * G1_STAGE;
#pragma unroll
        for (int it = 0; it < 4; ++it) {
            int c = tid + 256 * it, m = c >> 3, j = c & 7;
            int tok = pid_s[m] >> 1;
            size_t so = (size_t)tok * H_DIM + k0 + j * 8;
            uint32_t o = sw128((uint32_t)(m * 128 + j * 16));
            cp16(buf + o, g_hid_hi + so);
            cp16(buf + TILE_T + o, g_hid_lo + so);
        }
        cp_commit();
    };

    float cg[4][2][4] = {}, cu[4][2][4] = {};

    // A ldmatrix lane coords
    const int ar = lid & 15, ahh = lid >> 4;
    // B trans-ldmatrix lane coords
    const int btr = (lid & 7) + ((lid >> 3) & 1) * 8;
    const int btc = wn * 16 + (lid >> 4) * 8;

    const int S = H_DIM / KT;   // 16
    ldgB(0);
    prefA(0);
    for (int s = 0; s < S; ++s) {
        stsB(s);
        if (s + 1 < S) { prefA(s + 1); cp_wait<1>(); }
        else           { cp_wait<0>(); }
        __syncthreads();
        if (s + 1 < S) ldgB(s + 1);

        const uint32_t buf = sb + 1024 + (uint32_t)(s & 1) * G1_STAGE;
        const uint32_t bAh = buf, bAl = buf + TILE_T;
        const uint32_t bG = buf + 2 * TILE_T;
        const uint32_t bU = bG + BTILE_T;

#pragma unroll
        for (int ks = 0; ks < 4; ++ks) {
            uint32_t Ah[4][4], Al[4][4];
#pragma unroll
            for (int f = 0; f < 4; ++f) {
                uint32_t o = sw128((uint32_t)((wm * 64 + f * 16 + ar) * 128
                                              + ks * 32 + ahh * 16));
                LDSM4(Ah[f], bAh + o);
                LDSM4(Al[f], bAl + o);
            }
            uint32_t ob = sw128((uint32_t)((ks * 16 + btr) * 128 + btc * 2));
            uint32_t G[4], U[4];
            LDSM4T(G, bG + ob);
            LDSM4T(U, bU + ob);
#pragma unroll
            for (int f = 0; f < 4; ++f)
#pragma unroll
                for (int j = 0; j < 2; ++j) {
                    mma_f16(cg[f][j], Ah[f], G[2 * j], G[2 * j + 1]);
                    mma_f16(cg[f][j], Al[f], G[2 * j], G[2 * j + 1]);
                    mma_f16(cu[f][j], Ah[f], U[2 * j], U[2 * j + 1]);
                    mma_f16(cu[f][j], Al[f], U[2 * j], U[2 * j + 1]);
                }
        }
        __syncthreads();
    }

    // Epilogue: SwiGLU + fp16 hi/lo split
    const int rows = n_e - y0;
    const int coln = n0 + wn * 16 + (lid & 3) * 2;
#pragma unroll
    for (int f = 0; f < 4; ++f)
#pragma unroll
        for (int half_i = 0; half_i < 2; ++half_i) {
            int m = wm * 64 + f * 16 + (lid >> 2) + half_i * 8;
            if (m >= rows) continue;
            int pid = pid_s[m];
            fp16* dh = g_act_hi + (size_t)pid * I_DIM;
            fp16* dl = g_act_lo + (size_t)pid * I_DIM;
#pragma unroll
            for (int j = 0; j < 2; ++j) {
                float g0 = cg[f][j][2 * half_i], g1 = cg[f][j][2 * half_i + 1];
                float u0 = cu[f][j][2 * half_i], u1 = cu[f][j][2 * half_i + 1];
                float a0 = u0 * (g0 / (1.0f + __expf(-g0)));
                float a1 = u1 * (g1 / (1.0f + __expf(-g1)));
                fp16 h0 = __float2half_rn(a0);
                fp16 l0 = __float2half_rn(a0 - __half2float(h0));
                fp16 h1 = __float2half_rn(a1);
                fp16 l1 = __float2half_rn(a1 - __half2float(h1));
                *(__half2*)(dh + coln + j * 8) = __halves2half2(h0, h1);
                *(__half2*)(dl + coln + j * 8) = __halves2half2(l0, l1);
            }
        }
}

// ---------------------------------------------------------------------------
// GEMM2: CTA M=128 x N=128, 256 threads, warp = 64 x 32. K = 2816.
// A = split fp16 act, B = pre-transposed fp16 w2t, both via cp.async (R12).
// smem: 1024 + 2 x 48KB = 99328.
// ---------------------------------------------------------------------------
#define G2_STAGE (3 * TILE_T)                    // 48 KB
#define G2_SMEM  (1024 + 2 * G2_STAGE)

__global__ __launch_bounds__(256, 1) void gemm2_kernel()
{
    extern __shared__ char smem[];
    const uint32_t sb = s2u(smem);
    const int tid = threadIdx.x;
    const int lid = tid & 31, wid = tid >> 5;
    const int wm = wid >> 2;
    const int wn = wid & 3;           // 0..3 -> 32 cols
    const int e  = blockIdx.z;
    const int n_e = g_cnt[e];
    const int y0 = blockIdx.x * 128;
    if (y0 >= n_e) return;
    const int n0 = blockIdx.y * 128;

    int* pid_s = (int*)smem;
    if (tid < 128) {
        int r = y0 + tid;
        pid_s[tid] = (r < n_e) ? g_list[e * T_TOK + r] : 0;
    }
    __syncthreads();

    const size_t wb = (size_t)e * H_DIM * I_DIM;
    const fp16* bp = g_w2t + wb + (size_t)n0 * I_DIM;

    const uint32_t buf0 = sb + 1024;

    auto prefetch = [&](int s) {
        const int k0 = s * KT;
        const uint32_t buf = buf0 + (uint32_t)(s & 1) * G2_STAGE;
#pragma unroll
        for (int it = 0; it < 4; ++it) {
            int c = tid + 256 * it, m = c >> 3, j = c & 7;
            size_t so = (size_t)pid_s[m] * I_DIM + k0 + j * 8;
            uint32_t o = sw128((uint32_t)(m * 128 + j * 16));
            cp16(buf + o, g_act_hi + so);
            cp16(buf + TILE_T + o, g_act_lo + so);
        }
#pragma unroll
        for (int it = 0; it < 4; ++it) {
            int c = tid + 256 * it, n = c >> 3, j = c & 7;
            size_t ro = (size_t)n * I_DIM + k0 + j * 8;
            uint32_t o = sw128((uint32_t)(n * 128 + j * 16));
            cp16(buf + 2 * TILE_T + o, bp + ro);
        }
        cp_commit();
    };

    float acc[4][4][4] = {};

    const int ar = lid & 15, ahh = lid >> 4;
    const int bgp = lid >> 3, bj = lid & 7;
    const int brow0 = wn * 32 + ((bgp & 2) ? 8 : 0) + bj;
    const int bko = (bgp & 1) ? 16 : 0;

    const int S = I_DIM / KT;   // 44
    prefetch(0);
    for (int s = 0; s < S; ++s) {
        if (s + 1 < S) { prefetch(s + 1); cp_wait<1>(); }
        else           { cp_wait<0>(); }
        __syncthreads();

        const uint32_t buf = buf0 + (uint32_t)(s & 1) * G2_STAGE;
        const uint32_t bAh = buf, bAl = buf + TILE_T;
        const uint32_t bB = buf + 2 * TILE_T;

#pragma unroll
        for (int ks = 0; ks < 4; ++ks) {
            uint32_t Ah[4][4], Al[4][4];
#pragma unroll
            for (int f = 0; f < 4; ++f) {
                uint32_t o = sw128((uint32_t)((wm * 64 + f * 16 + ar) * 128
                                              + ks * 32 + ahh * 16));
                LDSM4(Ah[f], bAh + o);
                LDSM4(Al[f], bAl + o);
            }
            uint32_t B[8];
#pragma unroll
            for (int q = 0; q < 2; ++q) {
                uint32_t ob = sw128((uint32_t)((brow0 + q * 16) * 128
                                               + ks * 32 + bko));
                LDSM4(&B[4 * q], bB + ob);
            }
#pragma unroll
            for (int f = 0; f < 4; ++f)
#pragma unroll
                for (int j = 0; j < 4; ++j) {
                    int q = j >> 1, r2 = (j & 1) * 2;
                    mma_f16(acc[f][j], Ah[f], B[4 * q + r2], B[4 * q + r2 + 1]);
                    mma_f16(acc[f][j], Al[f], B[4 * q + r2], B[4 * q + r2 + 1]);
                }
        }
        __syncthreads();
    }

    const int rows = n_e - y0;
    const int colb = n0 + wn * 32 + (lid & 3) * 2;
#pragma unroll
    for (int f = 0; f < 4; ++f)
#pragma unroll
        for (int half_i = 0; half_i < 2; ++half_i) {
            int m = wm * 64 + f * 16 + (lid >> 2) + half_i * 8;
            if (m >= rows) continue;
            float* dst = g_eo + (size_t)pid_s[m] * H_DIM;
#pragma unroll
            for (int j = 0; j < 4; ++j) {
                float2 v = make_float2(acc[f][j][2 * half_i], acc[f][j][2 * half_i + 1]);
                *(float2*)(dst + colb + j * 8) = v;
            }
        }
}

// ---------------------------------------------------------------------------
// Combine
// ---------------------------------------------------------------------------
__global__ void combine_kernel(float* __restrict__ out)
{
    const int t = blockIdx.x;
    const float w0 = g_wt[2 * t];
    const float w1 = g_wt[2 * t + 1];
    const float4* a = (const float4*)(g_eo + (size_t)(2 * t) * H_DIM);
    const float4* b = (const float4*)(g_eo + (size_t)(2 * t + 1) * H_DIM);
    float4* o = (float4*)(out + (size_t)t * H_DIM);
    int i = threadIdx.x;
    float4 x = a[i], y = b[i];
    o[i] = make_float4(w0 * x.x + w1 * y.x,
                       w0 * x.y + w1 * y.y,
                       w0 * x.z + w1 * y.z,
                       w0 * x.w + w1 * y.w);
}

// ---------------------------------------------------------------------------
// Launch: prep (conv+router fused), trans_w2, gemm1, gemm2 (4th -> ncu slot),
// combine.
// ---------------------------------------------------------------------------
extern "C" void kernel_launch(void* const* d_in, const int* in_sizes, int n_in,
                              void* d_out, int out_size)
{
    const float* hidden = (const float*)d_in[0];   // [1024, 1024]
    const float* logits = (const float*)d_in[1];   // [1024, 8]
    const float* w13    = (const float*)d_in[2];   // [8, 1024, 5632]
    const float* w2     = (const float*)d_in[3];   // [8, 2816, 1024]
    float* out = (float*)d_out;

    cudaFuncSetAttribute(gemm1_kernel,
                         cudaFuncAttributeMaxDynamicSharedMemorySize, G1_SMEM);
    cudaFuncSetAttribute(gemm2_kernel,
                         cudaFuncAttributeMaxDynamicSharedMemorySize, G2_SMEM);

    prep_kernel<<<1025, 1024>>>(hidden, logits);

    dim3 gt2(H_DIM / 64, I_DIM / 64, E_NUM);       // 16 x 44 x 8
    trans_w2<<<gt2, 256>>>(w2);

    dim3 gg1(8, I_DIM / 64, E_NUM);     // 8 x 44 x 8
    gemm1_kernel<<<gg1, 256, G1_SMEM>>>(w13);

    dim3 gg2(8, H_DIM / 128, E_NUM);    // 8 x 8 x 8
    gemm2_kernel<<<gg2, 256, G2_SMEM>>>();

    combine_kernel<<<T_TOK, 256>>>(out);
}

// round 16
// speedup vs baseline: 1.1473x; 1.1473x over previous
#include <cuda_runtime.h>
#include <cuda_fp16.h>
#include <cstdint>
#include <cstddef>

typedef __half fp16;

#define T_TOK   1024
#define H_DIM   1024
#define I_DIM   2816
#define E_NUM   8
#define NPAIR   2048
#define W13_2I  5632
#define KSPLIT  2

// ---------------------------------------------------------------------------
// Device scratch (referenced ONLY from device code)
// ---------------------------------------------------------------------------
__device__ fp16 g_hid_hi[(size_t)T_TOK * H_DIM];
__device__ fp16 g_hid_lo[(size_t)T_TOK * H_DIM];
__device__ fp16 g_act_hi[(size_t)NPAIR * I_DIM];
__device__ fp16 g_act_lo[(size_t)NPAIR * I_DIM];
__device__ float g_eo   [(size_t)KSPLIT * NPAIR * H_DIM];  // split-K partials
__device__ float g_wt   [NPAIR];
__device__ int   g_cnt  [E_NUM];
__device__ int   g_list [E_NUM * T_TOK];

// ---------------------------------------------------------------------------
// PTX helpers (sm_80-compatible only)
// ---------------------------------------------------------------------------
__device__ __forceinline__ uint32_t s2u(const void* p) {
    uint32_t a;
    asm("{ .reg .u64 t; cvta.to.shared.u64 t, %1; cvt.u32.u64 %0, t; }"
        : "=r"(a) : "l"(p));
    return a;
}
__device__ __forceinline__ uint32_t sw128(uint32_t o) { return o ^ ((o >> 3) & 0x70); }

__device__ __forceinline__ void cp16(uint32_t dst, const void* src) {
    asm volatile("cp.async.cg.shared.global [%0], [%1], 16;" :: "r"(dst), "l"(src));
}
__device__ __forceinline__ void cp_commit() { asm volatile("cp.async.commit_group;"); }
template<int N> __device__ __forceinline__ void cp_wait() {
    asm volatile("cp.async.wait_group %0;" :: "n"(N));
}

#define LDSM4(r, addr) asm volatile( \
    "ldmatrix.sync.aligned.m8n8.x4.shared.b16 {%0,%1,%2,%3}, [%4];" \
    : "=r"((r)[0]), "=r"((r)[1]), "=r"((r)[2]), "=r"((r)[3]) : "r"(addr))

#define LDSM4T(r, addr) asm volatile( \
    "ldmatrix.sync.aligned.m8n8.x4.trans.shared.b16 {%0,%1,%2,%3}, [%4];" \
    : "=r"((r)[0]), "=r"((r)[1]), "=r"((r)[2]), "=r"((r)[3]) : "r"(addr))

__device__ __forceinline__ void mma_f16(float* c, const uint32_t* a,
                                        uint32_t b0, uint32_t b1) {
    asm volatile(
        "mma.sync.aligned.m16n8k16.row.col.f32.f16.f16.f32 "
        "{%0,%1,%2,%3}, {%4,%5,%6,%7}, {%8,%9}, {%0,%1,%2,%3};"
        : "+f"(c[0]), "+f"(c[1]), "+f"(c[2]), "+f"(c[3])
        : "r"(a[0]), "r"(a[1]), "r"(a[2]), "r"(a[3]), "r"(b0), "r"(b1));
}

__device__ __forceinline__ void sts8_h2(char* p, float x, float y, float z, float w) {
    __half2 h[2];
    h[0] = __floats2half2_rn(x, y);
    h[1] = __floats2half2_rn(z, w);
    *(uint2*)p = *(uint2*)h;
}

#define KT 64                 // fp16 per K-stage (128-byte rows)
#define TILE_T 16384          // 128 x 64 fp16
#define BTILE_T 8192          // 64 x 64 fp16

// ---------------------------------------------------------------------------
// Hidden fp32 -> fp16 hi/lo split
// ---------------------------------------------------------------------------
__global__ void conv_hidden(const float* __restrict__ h)
{
    int i = blockIdx.x * 256 + threadIdx.x;
    float v = h[i];
    fp16 hi = __float2half_rn(v);
    g_hid_hi[i] = hi;
    g_hid_lo[i] = __float2half_rn(v - __half2float(hi));
}

// ---------------------------------------------------------------------------
// Router
// ---------------------------------------------------------------------------
__global__ void router_kernel(const float* __restrict__ logits)
{
    int t = threadIdx.x;
    if (t < E_NUM) g_cnt[t] = 0;
    __syncthreads();

    float l[E_NUM];
#pragma unroll
    for (int i = 0; i < E_NUM; ++i) l[i] = logits[t * E_NUM + i];

    int i0 = 0;
#pragma unroll
    for (int i = 1; i < E_NUM; ++i) if (l[i] > l[i0]) i0 = i;
    int i1 = (i0 == 0) ? 1 : 0;
#pragma unroll
    for (int i = 0; i < E_NUM; ++i) {
        if (i == i0) continue;
        if (l[i] > l[i1]) i1 = i;
    }
    float e1 = expf(l[i1] - l[i0]);
    float w0 = 1.0f / (1.0f + e1);
    g_wt[2 * t]     = w0;
    g_wt[2 * t + 1] = 1.0f - w0;

    int s0 = atomicAdd(&g_cnt[i0], 1);
    g_list[i0 * T_TOK + s0] = 2 * t;
    int s1 = atomicAdd(&g_cnt[i1], 1);
    g_list[i1 * T_TOK + s1] = 2 * t + 1;
}

// ---------------------------------------------------------------------------
// GEMM1: CTA M=128 tokens, N=64 gate + 64 up cols. 256 threads (8 warps),
// warp = 64(M) x 16(N) of both gate and up. A = split fp16 via cp.async.
// B = fp32 weights loaded DIRECTLY from w13 [H,2I]:
// float4 LDG -> half2 STS into [k][n] SW128 tiles -> ldmatrix.x4.trans.
// smem: 1024 + 2 x 48KB = 99328.
// ---------------------------------------------------------------------------
#define G1_STAGE (2 * TILE_T + 2 * BTILE_T)      // 48 KB
#define G1_SMEM  (1024 + 2 * G1_STAGE)

__global__ __launch_bounds__(256, 1) void gemm1_kernel(const float* __restrict__ w13)
{
    extern __shared__ char smem[];
    const uint32_t sb = s2u(smem);
    const int tid = threadIdx.x;
    const int lid = tid & 31, wid = tid >> 5;
    const int wm = wid >> 2;          // 0..1 -> 64 rows
    const int wn = wid & 3;           // 0..3 -> 16 cols
    const int e  = blockIdx.z;
    const int n_e = g_cnt[e];
    const int y0 = blockIdx.x * 128;
    if (y0 >= n_e) return;
    const int n0 = blockIdx.y * 64;

    int* pid_s = (int*)smem;
    if (tid < 128) {
        int r = y0 + tid;
        pid_s[tid] = (r < n_e) ? g_list[e * T_TOK + r] : 0;
    }
    __syncthreads();

    const float* We = w13 + (size_t)e * H_DIM * W13_2I;

    const int bn4 = (tid & 15) * 4;
    const int bkb = tid >> 4;
    float4 rG[4], rU[4];

    auto ldgB = [&](int s) {
        const int k0 = s * KT;
#pragma unroll
        for (int p = 0; p < 4; ++p) {
            const float* src = We + (size_t)(k0 + bkb + 16 * p) * W13_2I + n0 + bn4;
            rG[p] = *(const float4*)src;
            rU[p] = *(const float4*)(src + I_DIM);
        }
    };
    auto stsB = [&](int s) {
        char* bufg = smem + 1024 + (s & 1) * G1_STAGE + 2 * TILE_T;
#pragma unroll
        for (int p = 0; p < 4; ++p) {
            uint32_t o = sw128((uint32_t)((bkb + 16 * p) * 128 + bn4 * 2));
            sts8_h2(bufg + o,           rG[p].x, rG[p].y, rG[p].z, rG[p].w);
            sts8_h2(bufg + BTILE_T + o, rU[p].x, rU[p].y, rU[p].z, rU[p].w);
        }
    };
    auto prefA = [&](int s) {
        const int k0 = s * KT;
        const uint32_t buf = sb + 1024 + (uint32_t)(s & 1) * G1_STAGE;
#pragma unroll
        for (int it = 0; it < 4; ++it) {
            int c = tid + 256 * it, m = c >> 3, j = c & 7;
            int tok = pid_s[m] >> 1;
            size_t so = (size_t)tok * H_DIM + k0 + j * 8;
            uint32_t o = sw128((uint32_t)(m * 128 + j * 16));
            cp16(buf + o, g_hid_hi + so);
            cp16(buf + TILE_T + o, g_hid_lo + so);
        }
        cp_commit();
    };

    float cg[4][2][4] = {}, cu[4][2][4] = {};

    const int ar = lid & 15, ahh = lid >> 4;
    const int btr = (lid & 7) + ((lid >> 3) & 1) * 8;
    const int btc = wn * 16 + (lid >> 4) * 8;

    const int S = H_DIM / KT;   // 16
    ldgB(0);
    prefA(0);
    for (int s = 0; s < S; ++s) {
        stsB(s);
        if (s + 1 < S) { prefA(s + 1); cp_wait<1>(); }
        else           { cp_wait<0>(); }
        __syncthreads();
        if (s + 1 < S) ldgB(s + 1);

        const uint32_t buf = sb + 1024 + (uint32_t)(s & 1) * G1_STAGE;
        const uint32_t bAh = buf, bAl = buf + TILE_T;
        const uint32_t bG = buf + 2 * TILE_T;
        const uint32_t bU = bG + BTILE_T;

#pragma unroll
        for (int ks = 0; ks < 4; ++ks) {
            uint32_t Ah[4][4], Al[4][4];
#pragma unroll
            for (int f = 0; f < 4; ++f) {
                uint32_t o = sw128((uint32_t)((wm * 64 + f * 16 + ar) * 128
                                              + ks * 32 + ahh * 16));
                LDSM4(Ah[f], bAh + o);
                LDSM4(Al[f], bAl + o);
            }
            uint32_t ob = sw128((uint32_t)((ks * 16 + btr) * 128 + btc * 2));
            uint32_t G[4], U[4];
            LDSM4T(G, bG + ob);
            LDSM4T(U, bU + ob);
#pragma unroll
            for (int f = 0; f < 4; ++f)
#pragma unroll
                for (int j = 0; j < 2; ++j) {
                    mma_f16(cg[f][j], Ah[f], G[2 * j], G[2 * j + 1]);
                    mma_f16(cg[f][j], Al[f], G[2 * j], G[2 * j + 1]);
                    mma_f16(cu[f][j], Ah[f], U[2 * j], U[2 * j + 1]);
                    mma_f16(cu[f][j], Al[f], U[2 * j], U[2 * j + 1]);
                }
        }
        __syncthreads();
    }

    // Epilogue: SwiGLU + fp16 hi/lo split
    const int rows = n_e - y0;
    const int coln = n0 + wn * 16 + (lid & 3) * 2;
#pragma unroll
    for (int f = 0; f < 4; ++f)
#pragma unroll
        for (int half_i = 0; half_i < 2; ++half_i) {
            int m = wm * 64 + f * 16 + (lid >> 2) + half_i * 8;
            if (m >= rows) continue;
            int pid = pid_s[m];
            fp16* dh = g_act_hi + (size_t)pid * I_DIM;
            fp16* dl = g_act_lo + (size_t)pid * I_DIM;
#pragma unroll
            for (int j = 0; j < 2; ++j) {
                float g0 = cg[f][j][2 * half_i], g1 = cg[f][j][2 * half_i + 1];
                float u0 = cu[f][j][2 * half_i], u1 = cu[f][j][2 * half_i + 1];
                float a0 = u0 * (g0 / (1.0f + __expf(-g0)));
                float a1 = u1 * (g1 / (1.0f + __expf(-g1)));
                fp16 h0 = __float2half_rn(a0);
                fp16 l0 = __float2half_rn(a0 - __half2float(h0));
                fp16 h1 = __float2half_rn(a1);
                fp16 l1 = __float2half_rn(a1 - __half2float(h1));
                *(__half2*)(dh + coln + j * 8) = __halves2half2(h0, h1);
                *(__half2*)(dl + coln + j * 8) = __halves2half2(l0, l1);
            }
        }
}

// ---------------------------------------------------------------------------
// GEMM2: CTA M=128 x N=128, 256 threads, warp = 64 x 32. SPLIT-K x2:
// grid z = E * 2; each CTA computes 22 of 44 K-stages into its partial
// buffer. B = fp32 w2 [I,H] direct load + convert (two 64-wide SW128
// subtiles per stage). smem: 1024 + 2 x 48KB = 99328.
// ---------------------------------------------------------------------------
#define G2_STAGE (3 * TILE_T)                    // 48 KB
#define G2_SMEM  (1024 + 2 * G2_STAGE)

__global__ __launch_bounds__(256, 1) void gemm2_kernel(const float* __restrict__ w2)
{
    extern __shared__ char smem[];
    const uint32_t sb = s2u(smem);
    const int tid = threadIdx.x;
    const int lid = tid & 31, wid = tid >> 5;
    const int wm = wid >> 2;          // 0..1 -> 64 rows
    const int wn = wid & 3;           // 0..3 -> 32 cols
    const int kz = blockIdx.z;
    const int e  = kz >> 1;
    const int kh = kz & 1;            // K half
    const int n_e = g_cnt[e];
    const int y0 = blockIdx.x * 128;
    if (y0 >= n_e) return;
    const int n0 = blockIdx.y * 128;

    int* pid_s = (int*)smem;
    if (tid < 128) {
        int r = y0 + tid;
        pid_s[tid] = (r < n_e) ? g_list[e * T_TOK + r] : 0;
    }
    __syncthreads();

    const float* We = w2 + (size_t)e * I_DIM * H_DIM;

    const int bn4 = (tid & 31) * 4;
    const int bkb = tid >> 5;
    const int bsub = bn4 >> 6;
    const int bnn = bn4 & 63;
    float4 rB[8];

    const int SH = (I_DIM / KT) / KSPLIT;   // 22 stages per half
    const int sbase = kh * SH;

    auto ldgB = [&](int si) {
        const int k0 = (sbase + si) * KT;
#pragma unroll
        for (int p = 0; p < 8; ++p)
            rB[p] = *(const float4*)(We + (size_t)(k0 + bkb + 8 * p) * H_DIM + n0 + bn4);
    };
    auto stsB = [&](int si) {
        char* buf = smem + 1024 + (si & 1) * G2_STAGE + 2 * TILE_T + bsub * 8192;
#pragma unroll
        for (int p = 0; p < 8; ++p) {
            uint32_t o = sw128((uint32_t)((bkb + 8 * p) * 128 + bnn * 2));
            sts8_h2(buf + o, rB[p].x, rB[p].y, rB[p].z, rB[p].w);
        }
    };
    auto prefA = [&](int si) {
        const int k0 = (sbase + si) * KT;
        const uint32_t buf = sb + 1024 + (uint32_t)(si & 1) * G2_STAGE;
#pragma unroll
        for (int it = 0; it < 4; ++it) {
            int c = tid + 256 * it, m = c >> 3, j = c & 7;
            size_t so = (size_t)pid_s[m] * I_DIM + k0 + j * 8;
            uint32_t o = sw128((uint32_t)(m * 128 + j * 16));
            cp16(buf + o, g_act_hi + so);
            cp16(buf + TILE_T + o, g_act_lo + so);
        }
        cp_commit();
    };

    float acc[4][4][4] = {};

    const int ar = lid & 15, ahh = lid >> 4;
    const int btr = (lid & 7) + ((lid >> 3) & 1) * 8;
    const int wsub = wn >> 1;
    const int wnb  = (wn & 1) * 32;
    const int btc8 = (lid >> 4) * 8;

    ldgB(0);
    prefA(0);
    for (int si = 0; si < SH; ++si) {
        stsB(si);
        if (si + 1 < SH) { prefA(si + 1); cp_wait<1>(); }
        else             { cp_wait<0>(); }
        __syncthreads();
        if (si + 1 < SH) ldgB(si + 1);

        const uint32_t buf = sb + 1024 + (uint32_t)(si & 1) * G2_STAGE;
        const uint32_t bAh = buf, bAl = buf + TILE_T;
        const uint32_t bB = buf + 2 * TILE_T + (uint32_t)wsub * 8192;

#pragma unroll
        for (int ks = 0; ks < 4; ++ks) {
            uint32_t Ah[4][4], Al[4][4];
#pragma unroll
            for (int f = 0; f < 4; ++f) {
                uint32_t o = sw128((uint32_t)((wm * 64 + f * 16 + ar) * 128
                                              + ks * 32 + ahh * 16));
                LDSM4(Ah[f], bAh + o);
                LDSM4(Al[f], bAl + o);
            }
            uint32_t B[8];
#pragma unroll
            for (int q = 0; q < 2; ++q) {
                uint32_t ob = sw128((uint32_t)((ks * 16 + btr) * 128
                                               + (wnb + q * 16 + btc8) * 2));
                LDSM4T(&B[4 * q], bB + ob);
            }
#pragma unroll
            for (int f = 0; f < 4; ++f)
#pragma unroll
                for (int j = 0; j < 4; ++j) {
                    int q = j >> 1, r2 = (j & 1) * 2;
                    mma_f16(acc[f][j], Ah[f], B[4 * q + r2], B[4 * q + r2 + 1]);
                    mma_f16(acc[f][j], Al[f], B[4 * q + r2], B[4 * q + r2 + 1]);
                }
        }
        __syncthreads();
    }

    const int rows = n_e - y0;
    const int colb = n0 + wn * 32 + (lid & 3) * 2;
    float* eo = g_eo + (size_t)kh * NPAIR * H_DIM;
#pragma unroll
    for (int f = 0; f < 4; ++f)
#pragma unroll
        for (int half_i = 0; half_i < 2; ++half_i) {
            int m = wm * 64 + f * 16 + (lid >> 2) + half_i * 8;
            if (m >= rows) continue;
            float* dst = eo + (size_t)pid_s[m] * H_DIM;
#pragma unroll
            for (int j = 0; j < 4; ++j) {
                float2 v = make_float2(acc[f][j][2 * half_i], acc[f][j][2 * half_i + 1]);
                *(float2*)(dst + colb + j * 8) = v;
            }
        }
}

// ---------------------------------------------------------------------------
// Combine: out[t] = w0*(eo0[2t]+eo1[2t]) + w1*(eo0[2t+1]+eo1[2t+1])
// ---------------------------------------------------------------------------
__global__ void combine_kernel(float* __restrict__ out)
{
    const int t = blockIdx.x;
    const float w0 = g_wt[2 * t];
    const float w1 = g_wt[2 * t + 1];
    const size_t off1 = (size_t)NPAIR * H_DIM;
    const float4* a0 = (const float4*)(g_eo + (size_t)(2 * t) * H_DIM);
    const float4* a1 = (const float4*)(g_eo + off1 + (size_t)(2 * t) * H_DIM);
    const float4* b0 = (const float4*)(g_eo + (size_t)(2 * t + 1) * H_DIM);
    const float4* b1 = (const float4*)(g_eo + off1 + (size_t)(2 * t + 1) * H_DIM);
    float4* o = (float4*)(out + (size_t)t * H_DIM);
    int i = threadIdx.x;
    float4 xa = a0[i], xb = a1[i], ya = b0[i], yb = b1[i];
    o[i] = make_float4(w0 * (xa.x + xb.x) + w1 * (ya.x + yb.x),
                       w0 * (xa.y + xb.y) + w1 * (ya.y + yb.y),
                       w0 * (xa.z + xb.z) + w1 * (ya.z + yb.z),
                       w0 * (xa.w + xb.w) + w1 * (ya.w + yb.w));
}

// ---------------------------------------------------------------------------
// Launch: conv(1) router(2) gemm1(3) gemm2(4 -> ncu slot) combine(5).
// ---------------------------------------------------------------------------
extern "C" void kernel_launch(void* const* d_in, const int* in_sizes, int n_in,
                              void* d_out, int out_size)
{
    const float* hidden = (const float*)d_in[0];   // [1024, 1024]
    const float* logits = (const float*)d_in[1];   // [1024, 8]
    const float* w13    = (const float*)d_in[2];   // [8, 1024, 5632]
    const float* w2     = (const float*)d_in[3];   // [8, 2816, 1024]
    float* out = (float*)d_out;

    cudaFuncSetAttribute(gemm1_kernel,
                         cudaFuncAttributeMaxDynamicSharedMemorySize, G1_SMEM);
    cudaFuncSetAttribute(gemm2_kernel,
                         cudaFuncAttributeMaxDynamicSharedMemorySize, G2_SMEM);

    conv_hidden<<<(T_TOK * H_DIM) / 256, 256>>>(hidden);
    router_kernel<<<1, T_TOK>>>(logits);

    dim3 gg1(8, I_DIM / 64, E_NUM);             // 8 x 44 x 8
    gemm1_kernel<<<gg1, 256, G1_SMEM>>>(w13);

    dim3 gg2(8, H_DIM / 128, E_NUM * KSPLIT);   // 8 x 8 x 16
    gemm2_kernel<<<gg2, 256, G2_SMEM>>>(w2);

    combine_kernel<<<T_TOK, 256>>>(out);
}

// round 17
// speedup vs baseline: 1.1916x; 1.0386x over previous
#include <cuda_runtime.h>
#include <cuda_fp16.h>
#include <cstdint>
#include <cstddef>

typedef __half fp16;

#define T_TOK   1024
#define H_DIM   1024
#define I_DIM   2816
#define E_NUM   8
#define NPAIR   2048
#define W13_2I  5632
#define KSPLIT  4

// ---------------------------------------------------------------------------
// Device scratch (referenced ONLY from device code)
// ---------------------------------------------------------------------------
__device__ fp16 g_hid_hi[(size_t)T_TOK * H_DIM];
__device__ fp16 g_hid_lo[(size_t)T_TOK * H_DIM];
__device__ fp16 g_act_hi[(size_t)NPAIR * I_DIM];
__device__ fp16 g_act_lo[(size_t)NPAIR * I_DIM];
__device__ float g_eo   [(size_t)KSPLIT * NPAIR * H_DIM];  // split-K partials
__device__ float g_wt   [NPAIR];
__device__ int   g_cnt  [E_NUM];
__device__ int   g_list [E_NUM * T_TOK];

// ---------------------------------------------------------------------------
// PTX helpers (sm_80-compatible only)
// ---------------------------------------------------------------------------
__device__ __forceinline__ uint32_t s2u(const void* p) {
    uint32_t a;
    asm("{ .reg .u64 t; cvta.to.shared.u64 t, %1; cvt.u32.u64 %0, t; }"
        : "=r"(a) : "l"(p));
    return a;
}
__device__ __forceinline__ uint32_t sw128(uint32_t o) { return o ^ ((o >> 3) & 0x70); }

__device__ __forceinline__ void cp16(uint32_t dst, const void* src) {
    asm volatile("cp.async.cg.shared.global [%0], [%1], 16;" :: "r"(dst), "l"(src));
}
__device__ __forceinline__ void cp_commit() { asm volatile("cp.async.commit_group;"); }
template<int N> __device__ __forceinline__ void cp_wait() {
    asm volatile("cp.async.wait_group %0;" :: "n"(N));
}

#define LDSM4(r, addr) asm volatile( \
    "ldmatrix.sync.aligned.m8n8.x4.shared.b16 {%0,%1,%2,%3}, [%4];" \
    : "=r"((r)[0]), "=r"((r)[1]), "=r"((r)[2]), "=r"((r)[3]) : "r"(addr))

#define LDSM4T(r, addr) asm volatile( \
    "ldmatrix.sync.aligned.m8n8.x4.trans.shared.b16 {%0,%1,%2,%3}, [%4];" \
    : "=r"((r)[0]), "=r"((r)[1]), "=r"((r)[2]), "=r"((r)[3]) : "r"(addr))

__device__ __forceinline__ void mma_f16(float* c, const uint32_t* a,
                                        uint32_t b0, uint32_t b1) {
    asm volatile(
        "mma.sync.aligned.m16n8k16.row.col.f32.f16.f16.f32 "
        "{%0,%1,%2,%3}, {%4,%5,%6,%7}, {%8,%9}, {%0,%1,%2,%3};"
        : "+f"(c[0]), "+f"(c[1]), "+f"(c[2]), "+f"(c[3])
        : "r"(a[0]), "r"(a[1]), "r"(a[2]), "r"(a[3]), "r"(b0), "r"(b1));
}

__device__ __forceinline__ void sts8_h2(char* p, float x, float y, float z, float w) {
    __half2 h[2];
    h[0] = __floats2half2_rn(x, y);
    h[1] = __floats2half2_rn(z, w);
    *(uint2*)p = *(uint2*)h;
}

#define KT 64                 // fp16 per K-stage (128-byte rows)
#define TILE_T 16384          // 128 x 64 fp16
#define BTILE_T 8192          // 64 x 64 fp16

// ---------------------------------------------------------------------------
// Hidden fp32 -> fp16 hi/lo split
// ---------------------------------------------------------------------------
__global__ void conv_hidden(const float* __restrict__ h)
{
    int i = blockIdx.x * 256 + threadIdx.x;
    float v = h[i];
    fp16 hi = __float2half_rn(v);
    g_hid_hi[i] = hi;
    g_hid_lo[i] = __float2half_rn(v - __half2float(hi));
}

// ---------------------------------------------------------------------------
// Router
// ---------------------------------------------------------------------------
__global__ void router_kernel(const float* __restrict__ logits)
{
    int t = threadIdx.x;
    if (t < E_NUM) g_cnt[t] = 0;
    __syncthreads();

    float l[E_NUM];
#pragma unroll
    for (int i = 0; i < E_NUM; ++i) l[i] = logits[t * E_NUM + i];

    int i0 = 0;
#pragma unroll
    for (int i = 1; i < E_NUM; ++i) if (l[i] > l[i0]) i0 = i;
    int i1 = (i0 == 0) ? 1 : 0;
#pragma unroll
    for (int i = 0; i < E_NUM; ++i) {
        if (i == i0) continue;
        if (l[i] > l[i1]) i1 = i;
    }
    float e1 = expf(l[i1] - l[i0]);
    float w0 = 1.0f / (1.0f + e1);
    g_wt[2 * t]     = w0;
    g_wt[2 * t + 1] = 1.0f - w0;

    int s0 = atomicAdd(&g_cnt[i0], 1);
    g_list[i0 * T_TOK + s0] = 2 * t;
    int s1 = atomicAdd(&g_cnt[i1], 1);
    g_list[i1 * T_TOK + s1] = 2 * t + 1;
}

// ---------------------------------------------------------------------------
// GEMM1: CTA M=128 tokens, N=64 gate + 64 up cols. 256 threads (8 warps),
// warp = 64(M) x 16(N) of both gate and up. A = split fp16 via cp.async.
// B = fp32 weights loaded DIRECTLY from w13 [H,2I]:
// float4 LDG -> half2 STS into [k][n] SW128 tiles -> ldmatrix.x4.trans.
// smem: 1024 + 2 x 48KB = 99328.
// ---------------------------------------------------------------------------
#define G1_STAGE (2 * TILE_T + 2 * BTILE_T)      // 48 KB
#define G1_SMEM  (1024 + 2 * G1_STAGE)

__global__ __launch_bounds__(256, 1) void gemm1_kernel(const float* __restrict__ w13)
{
    extern __shared__ char smem[];
    const uint32_t sb = s2u(smem);
    const int tid = threadIdx.x;
    const int lid = tid & 31, wid = tid >> 5;
    const int wm = wid >> 2;          // 0..1 -> 64 rows
    const int wn = wid & 3;           // 0..3 -> 16 cols
    const int e  = blockIdx.z;
    const int n_e = g_cnt[e];
    const int y0 = blockIdx.x * 128;
    if (y0 >= n_e) return;
    const int n0 = blockIdx.y * 64;

    int* pid_s = (int*)smem;
    if (tid < 128) {
        int r = y0 + tid;
        pid_s[tid] = (r < n_e) ? g_list[e * T_TOK + r] : 0;
    }
    __syncthreads();

    const float* We = w13 + (size_t)e * H_DIM * W13_2I;

    const int bn4 = (tid & 15) * 4;
    const int bkb = tid >> 4;
    float4 rG[4], rU[4];

    auto ldgB = [&](int s) {
        const int k0 = s * KT;
#pragma unroll
        for (int p = 0; p < 4; ++p) {
            const float* src = We + (size_t)(k0 + bkb + 16 * p) * W13_2I + n0 + bn4;
            rG[p] = *(const float4*)src;
            rU[p] = *(const float4*)(src + I_DIM);
        }
    };
    auto stsB = [&](int s) {
        char* bufg = smem + 1024 + (s & 1) * G1_STAGE + 2 * TILE_T;
#pragma unroll
        for (int p = 0; p < 4; ++p) {
            uint32_t o = sw128((uint32_t)((bkb + 16 * p) * 128 + bn4 * 2));
            sts8_h2(bufg + o,           rG[p].x, rG[p].y, rG[p].z, rG[p].w);
            sts8_h2(bufg + BTILE_T + o, rU[p].x, rU[p].y, rU[p].z, rU[p].w);
        }
    };
    auto prefA = [&](int s) {
        const int k0 = s * KT;
        const uint32_t buf = sb + 1024 + (uint32_t)(s & 1) * G1_STAGE;
#pragma unroll
        for (int it = 0; it < 4; ++it) {
            int c = tid + 256 * it, m = c >> 3, j = c & 7;
            int tok = pid_s[m] >> 1;
            size_t so = (size_t)tok * H_DIM + k0 + j * 8;
            uint32_t o = sw128((uint32_t)(m * 128 + j * 16));
            cp16(buf + o, g_hid_hi + so);
            cp16(buf + TILE_T + o, g_hid_lo + so);
        }
        cp_commit();
    };

    float cg[4][2][4] = {}, cu[4][2][4] = {};

    const int ar = lid & 15, ahh = lid >> 4;
    const int btr = (lid & 7) + ((lid >> 3) & 1) * 8;
    const int btc = wn * 16 + (lid >> 4) * 8;

    const int S = H_DIM / KT;   // 16
    ldgB(0);
    prefA(0);
    for (int s = 0; s < S; ++s) {
        stsB(s);
        if (s + 1 < S) { prefA(s + 1); cp_wait<1>(); }
        else           { cp_wait<0>(); }
        __syncthreads();
        if (s + 1 < S) ldgB(s + 1);

        const uint32_t buf = sb + 1024 + (uint32_t)(s & 1) * G1_STAGE;
        const uint32_t bAh = buf, bAl = buf + TILE_T;
        const uint32_t bG = buf + 2 * TILE_T;
        const uint32_t bU = bG + BTILE_T;

#pragma unroll
        for (int ks = 0; ks < 4; ++ks) {
            uint32_t Ah[4][4], Al[4][4];
#pragma unroll
            for (int f = 0; f < 4; ++f) {
                uint32_t o = sw128((uint32_t)((wm * 64 + f * 16 + ar) * 128
                                              + ks * 32 + ahh * 16));
                LDSM4(Ah[f], bAh + o);
                LDSM4(Al[f], bAl + o);
            }
            uint32_t ob = sw128((uint32_t)((ks * 16 + btr) * 128 + btc * 2));
            uint32_t G[4], U[4];
            LDSM4T(G, bG + ob);
            LDSM4T(U, bU + ob);
#pragma unroll
            for (int f = 0; f < 4; ++f)
#pragma unroll
                for (int j = 0; j < 2; ++j) {
                    mma_f16(cg[f][j], Ah[f], G[2 * j], G[2 * j + 1]);
                    mma_f16(cg[f][j], Al[f], G[2 * j], G[2 * j + 1]);
                    mma_f16(cu[f][j], Ah[f], U[2 * j], U[2 * j + 1]);
                    mma_f16(cu[f][j], Al[f], U[2 * j], U[2 * j + 1]);
                }
        }
        __syncthreads();
    }

    // Epilogue: SwiGLU + fp16 hi/lo split
    const int rows = n_e - y0;
    const int coln = n0 + wn * 16 + (lid & 3) * 2;
#pragma unroll
    for (int f = 0; f < 4; ++f)
#pragma unroll
        for (int half_i = 0; half_i < 2; ++half_i) {
            int m = wm * 64 + f * 16 + (lid >> 2) + half_i * 8;
            if (m >= rows) continue;
            int pid = pid_s[m];
            fp16* dh = g_act_hi + (size_t)pid * I_DIM;
            fp16* dl = g_act_lo + (size_t)pid * I_DIM;
#pragma unroll
            for (int j = 0; j < 2; ++j) {
                float g0 = cg[f][j][2 * half_i], g1 = cg[f][j][2 * half_i + 1];
                float u0 = cu[f][j][2 * half_i], u1 = cu[f][j][2 * half_i + 1];
                float a0 = u0 * (g0 / (1.0f + __expf(-g0)));
                float a1 = u1 * (g1 / (1.0f + __expf(-g1)));
                fp16 h0 = __float2half_rn(a0);
                fp16 l0 = __float2half_rn(a0 - __half2float(h0));
                fp16 h1 = __float2half_rn(a1);
                fp16 l1 = __float2half_rn(a1 - __half2float(h1));
                *(__half2*)(dh + coln + j * 8) = __halves2half2(h0, h1);
                *(__half2*)(dl + coln + j * 8) = __halves2half2(l0, l1);
            }
        }
}

// ---------------------------------------------------------------------------
// GEMM2: CTA M=128 x N=128, 256 threads, warp = 64 x 32. SPLIT-K x4:
// grid z = E * 4; each CTA computes 11 of 44 K-stages into its partial
// buffer. B = fp32 w2 [I,H] direct load + convert. smem: 99328.
// ---------------------------------------------------------------------------
#define G2_STAGE (3 * TILE_T)                    // 48 KB
#define G2_SMEM  (1024 + 2 * G2_STAGE)

__global__ __launch_bounds__(256, 1) void gemm2_kernel(const float* __restrict__ w2)
{
    extern __shared__ char smem[];
    const uint32_t sb = s2u(smem);
    const int tid = threadIdx.x;
    const int lid = tid & 31, wid = tid >> 5;
    const int wm = wid >> 2;          // 0..1 -> 64 rows
    const int wn = wid & 3;           // 0..3 -> 32 cols
    const int kz = blockIdx.z;
    const int e  = kz >> 2;
    const int kh = kz & 3;            // K quarter
    const int n_e = g_cnt[e];
    const int y0 = blockIdx.x * 128;
    if (y0 >= n_e) return;
    const int n0 = blockIdx.y * 128;

    int* pid_s = (int*)smem;
    if (tid < 128) {
        int r = y0 + tid;
        pid_s[tid] = (r < n_e) ? g_list[e * T_TOK + r] : 0;
    }
    __syncthreads();

    const float* We = w2 + (size_t)e * I_DIM * H_DIM;

    const int bn4 = (tid & 31) * 4;
    const int bkb = tid >> 5;
    const int bsub = bn4 >> 6;
    const int bnn = bn4 & 63;
    float4 rB[8];

    const int SH = (I_DIM / KT) / KSPLIT;   // 11 stages per quarter
    const int sbase = kh * SH;

    auto ldgB = [&](int si) {
        const int k0 = (sbase + si) * KT;
#pragma unroll
        for (int p = 0; p < 8; ++p)
            rB[p] = *(const float4*)(We + (size_t)(k0 + bkb + 8 * p) * H_DIM + n0 + bn4);
    };
    auto stsB = [&](int si) {
        char* buf = smem + 1024 + (si & 1) * G2_STAGE + 2 * TILE_T + bsub * 8192;
#pragma unroll
        for (int p = 0; p < 8; ++p) {
            uint32_t o = sw128((uint32_t)((bkb + 8 * p) * 128 + bnn * 2));
            sts8_h2(buf + o, rB[p].x, rB[p].y, rB[p].z, rB[p].w);
        }
    };
    auto prefA = [&](int si) {
        const int k0 = (sbase + si) * KT;
        const uint32_t buf = sb + 1024 + (uint32_t)(si & 1) * G2_STAGE;
#pragma unroll
        for (int it = 0; it < 4; ++it) {
            int c = tid + 256 * it, m = c >> 3, j = c & 7;
            size_t so = (size_t)pid_s[m] * I_DIM + k0 + j * 8;
            uint32_t o = sw128((uint32_t)(m * 128 + j * 16));
            cp16(buf + o, g_act_hi + so);
            cp16(buf + TILE_T + o, g_act_lo + so);
        }
        cp_commit();
    };

    float acc[4][4][4] = {};

    const int ar = lid & 15, ahh = lid >> 4;
    const int btr = (lid & 7) + ((lid >> 3) & 1) * 8;
    const int wsub = wn >> 1;
    const int wnb  = (wn & 1) * 32;
    const int btc8 = (lid >> 4) * 8;

    ldgB(0);
    prefA(0);
    for (int si = 0; si < SH; ++si) {
        stsB(si);
        if (si + 1 < SH) { prefA(si + 1); cp_wait<1>(); }
        else             { cp_wait<0>(); }
        __syncthreads();
        if (si + 1 < SH) ldgB(si + 1);

        const uint32_t buf = sb + 1024 + (uint32_t)(si & 1) * G2_STAGE;
        const uint32_t bAh = buf, bAl = buf + TILE_T;
        const uint32_t bB = buf + 2 * TILE_T + (uint32_t)wsub * 8192;

#pragma unroll
        for (int ks = 0; ks < 4; ++ks) {
            uint32_t Ah[4][4], Al[4][4];
#pragma unroll
            for (int f = 0; f < 4; ++f) {
                uint32_t o = sw128((uint32_t)((wm * 64 + f * 16 + ar) * 128
                                              + ks * 32 + ahh * 16));
                LDSM4(Ah[f], bAh + o);
                LDSM4(Al[f], bAl + o);
            }
            uint32_t B[8];
#pragma unroll
            for (int q = 0; q < 2; ++q) {
                uint32_t ob = sw128((uint32_t)((ks * 16 + btr) * 128
                                               + (wnb + q * 16 + btc8) * 2));
                LDSM4T(&B[4 * q], bB + ob);
            }
#pragma unroll
            for (int f = 0; f < 4; ++f)
#pragma unroll
                for (int j = 0; j < 4; ++j) {
                    int q = j >> 1, r2 = (j & 1) * 2;
                    mma_f16(acc[f][j], Ah[f], B[4 * q + r2], B[4 * q + r2 + 1]);
                    mma_f16(acc[f][j], Al[f], B[4 * q + r2], B[4 * q + r2 + 1]);
                }
        }
        __syncthreads();
    }

    const int rows = n_e - y0;
    const int colb = n0 + wn * 32 + (lid & 3) * 2;
    float* eo = g_eo + (size_t)kh * NPAIR * H_DIM;
#pragma unroll
    for (int f = 0; f < 4; ++f)
#pragma unroll
        for (int half_i = 0; half_i < 2; ++half_i) {
            int m = wm * 64 + f * 16 + (lid >> 2) + half_i * 8;
            if (m >= rows) continue;
            float* dst = eo + (size_t)pid_s[m] * H_DIM;
#pragma unroll
            for (int j = 0; j < 4; ++j) {
                float2 v = make_float2(acc[f][j][2 * half_i], acc[f][j][2 * half_i + 1]);
                *(float2*)(dst + colb + j * 8) = v;
            }
        }
}

// ---------------------------------------------------------------------------
// Combine: out[t] = w0 * sum_k eo_k[2t] + w1 * sum_k eo_k[2t+1]
// ---------------------------------------------------------------------------
__global__ void combine_kernel(float* __restrict__ out)
{
    const int t = blockIdx.x;
    const float w0 = g_wt[2 * t];
    const float w1 = g_wt[2 * t + 1];
    const size_t stride = (size_t)NPAIR * H_DIM;
    int i = threadIdx.x;

    float4 xa = make_float4(0.f, 0.f, 0.f, 0.f);
    float4 ya = make_float4(0.f, 0.f, 0.f, 0.f);
#pragma unroll
    for (int k = 0; k < KSPLIT; ++k) {
        const float4* a = (const float4*)(g_eo + k * stride + (size_t)(2 * t) * H_DIM);
        const float4* b = (const float4*)(g_eo + k * stride + (size_t)(2 * t + 1) * H_DIM);
        float4 av = a[i], bv = b[i];
        xa.x += av.x; xa.y += av.y; xa.z += av.z; xa.w += av.w;
        ya.x += bv.x; ya.y += bv.y; ya.z += bv.z; ya.w += bv.w;
    }
    float4* o = (float4*)(out + (size_t)t * H_DIM);
    o[i] = make_float4(w0 * xa.x + w1 * ya.x,
                       w0 * xa.y + w1 * ya.y,
                       w0 * xa.z + w1 * ya.z,
                       w0 * xa.w + w1 * ya.w);
}

// ---------------------------------------------------------------------------
// Launch: conv(1) router(2) gemm1(3) gemm2(4 -> ncu slot) combine(5).
// ---------------------------------------------------------------------------
extern "C" void kernel_launch(void* const* d_in, const int* in_sizes, int n_in,
                              void* d_out, int out_size)
{
    const float* hidden = (const float*)d_in[0];   // [1024, 1024]
    const float* logits = (const float*)d_in[1];   // [1024, 8]
    const float* w13    = (const float*)d_in[2];   // [8, 1024, 5632]
    const float* w2     = (const float*)d_in[3];   // [8, 2816, 1024]
    float* out = (float*)d_out;

    cudaFuncSetAttribute(gemm1_kernel,
                         cudaFuncAttributeMaxDynamicSharedMemorySize, G1_SMEM);
    cudaFuncSetAttribute(gemm2_kernel,
                         cudaFuncAttributeMaxDynamicSharedMemorySize, G2_SMEM);

    conv_hidden<<<(T_TOK * H_DIM) / 256, 256>>>(hidden);
    router_kernel<<<1, T_TOK>>>(logits);

    dim3 gg1(8, I_DIM / 64, E_NUM);             // 8 x 44 x 8
    gemm1_kernel<<<gg1, 256, G1_SMEM>>>(w13);

    dim3 gg2(8, H_DIM / 128, E_NUM * KSPLIT);   // 8 x 8 x 32
    gemm2_kernel<<<gg2, 256, G2_SMEM>>>(w2);

    combine_kernel<<<T_TOK, 256>>>(out);
}